// round 1
// baseline (speedup 1.0000x reference)
#include <cuda_runtime.h>
#include <math.h>

// Problem constants
#define Bn   4
#define Nn   2048
#define Dn   512
#define Hn   8
#define DHn  64
#define Mn   (Bn * Nn)      // 8192 rows
#define QKVT_N 2048
#define CAT_N  1024

// Scratch (device globals — allocation-free per harness rules)
__device__ float g_qkvt[Mn * QKVT_N];   // 64 MB
__device__ float g_cat [Mn * CAT_N];    // 32 MB
__device__ float g_rinv[Nn];

// ---------------------------------------------------------------------------
// rinv[j] = 1 / sum_k exp(-|j-k|/e), closed form in fp64.
// ---------------------------------------------------------------------------
__global__ void rinv_kernel() {
    int j = blockIdx.x * blockDim.x + threadIdx.x;
    if (j >= Nn) return;
    const double la = -0.36787944117144233;   // -1/e
    const double a  =  0.6922006275553464;    // exp(-1/e)
    double s = 1.0
             + a * (1.0 - exp(la * (double)j))          / (1.0 - a)
             + a * (1.0 - exp(la * (double)(Nn - 1 - j))) / (1.0 - a);
    g_rinv[j] = (float)(1.0 / s);
}

// ---------------------------------------------------------------------------
// SGEMM: C[M,N] = A[M,K] @ B[K,N] (+ bias). 128x128x8 tiles, 8x8/thread.
// Requires M%128==0, N%128==0, K%8==0 (true for both calls).
// ---------------------------------------------------------------------------
__global__ __launch_bounds__(256) void sgemm128(
    const float* __restrict__ A, const float* __restrict__ B,
    float* __restrict__ C, const float* __restrict__ bias,
    int M, int N, int K)
{
    __shared__ float As[8 * 128];   // transposed: As[k*128 + m]
    __shared__ float Bs[8 * 128];   // Bs[k*128 + n]

    const int tid  = threadIdx.x;
    const int brow = blockIdx.y * 128;
    const int bcol = blockIdx.x * 128;

    const int a_r = tid >> 1,  a_c = (tid & 1) << 2;
    const int b_r = tid >> 5,  b_c = (tid & 31) << 2;

    const float* Aptr = A + (size_t)(brow + a_r) * K + a_c;
    const float* Bptr = B + (size_t)b_r * N + bcol + b_c;

    float4 aF = *(const float4*)Aptr;
    float4 bF = *(const float4*)Bptr;

    float acc[8][8];
    #pragma unroll
    for (int i = 0; i < 8; i++)
        #pragma unroll
        for (int j = 0; j < 8; j++) acc[i][j] = 0.f;

    const int ty = tid >> 4, tx = tid & 15;

    for (int k0 = 0; k0 < K; k0 += 8) {
        As[(a_c + 0) * 128 + a_r] = aF.x;
        As[(a_c + 1) * 128 + a_r] = aF.y;
        As[(a_c + 2) * 128 + a_r] = aF.z;
        As[(a_c + 3) * 128 + a_r] = aF.w;
        *(float4*)&Bs[b_r * 128 + b_c] = bF;
        __syncthreads();

        if (k0 + 8 < K) {
            aF = *(const float4*)(Aptr + k0 + 8);
            bF = *(const float4*)(Bptr + (size_t)(k0 + 8) * N);
        }

        #pragma unroll
        for (int k = 0; k < 8; k++) {
            float ar[8], br[8];
            #pragma unroll
            for (int i = 0; i < 8; i++) ar[i] = As[k * 128 + ty * 8 + i];
            #pragma unroll
            for (int j = 0; j < 8; j++) br[j] = Bs[k * 128 + tx * 8 + j];
            #pragma unroll
            for (int i = 0; i < 8; i++)
                #pragma unroll
                for (int j = 0; j < 8; j++)
                    acc[i][j] = fmaf(ar[i], br[j], acc[i][j]);
        }
        __syncthreads();
    }

    #pragma unroll
    for (int i = 0; i < 8; i++) {
        const size_t r = (size_t)(brow + ty * 8 + i);
        #pragma unroll
        for (int j = 0; j < 8; j += 4) {
            const int c = bcol + tx * 8 + j;
            float4 v;
            v.x = acc[i][j + 0]; v.y = acc[i][j + 1];
            v.z = acc[i][j + 2]; v.w = acc[i][j + 3];
            if (bias) {
                v.x += bias[c + 0]; v.y += bias[c + 1];
                v.z += bias[c + 2]; v.w += bias[c + 3];
            }
            *(float4*)&C[r * N + c] = v;
        }
    }
}

// ---------------------------------------------------------------------------
// Flash attention (branch 1), fp32. BR=128 query rows, BC=64 key cols, DH=64.
// Grid: (Nn/128, Bn*Hn). 256 threads: ty=tid/16 (8 rows), tx=tid%16 (4 cols).
// Output into g_cat[row, h*128 + d].
// ---------------------------------------------------------------------------
__global__ __launch_bounds__(256, 2) void flash_kernel(
    const float* __restrict__ qkvt, float* __restrict__ cat)
{
    constexpr int BR = 128, BC = 64, LD = 65;
    extern __shared__ float smf[];
    float* Qs = smf;                 // BR*LD
    float* Ks = Qs + BR * LD;        // BC*LD
    float* Vs = Ks + BC * LD;        // BC*LD
    float* Ps = Vs + BC * LD;        // BR*LD

    const int tid = threadIdx.x;
    const int bh  = blockIdx.y;
    const int b   = bh >> 3, h = bh & 7;
    const int i0  = blockIdx.x * BR;
    const float scale = 0.125f;      // 1/sqrt(64)

    const size_t rowbase = (size_t)b * Nn;
    const float* Qg = qkvt + (rowbase + i0) * QKVT_N + h * 64;          // q cols
    const float* Kg = qkvt + rowbase * QKVT_N + 512  + h * 64;          // k cols
    const float* Vg = qkvt + rowbase * QKVT_N + 1024 + h * 64;          // v cols

    // Load Q tile (pre-scaled)
    for (int p = tid; p < BR * 16; p += 256) {
        int r = p >> 4, c = (p & 15) << 2;
        float4 v = *(const float4*)(Qg + (size_t)r * QKVT_N + c);
        Qs[r * LD + c + 0] = v.x * scale;
        Qs[r * LD + c + 1] = v.y * scale;
        Qs[r * LD + c + 2] = v.z * scale;
        Qs[r * LD + c + 3] = v.w * scale;
    }

    const int ty = tid >> 4, tx = tid & 15;

    float O[8][4];
    float m[8], l[8];
    #pragma unroll
    for (int i = 0; i < 8; i++) {
        m[i] = -1e30f; l[i] = 0.f;
        #pragma unroll
        for (int j = 0; j < 4; j++) O[i][j] = 0.f;
    }

    for (int kt = 0; kt < Nn; kt += BC) {
        // Load K, V tiles
        for (int p = tid; p < BC * 16; p += 256) {
            int r = p >> 4, c = (p & 15) << 2;
            float4 kv = *(const float4*)(Kg + (size_t)(kt + r) * QKVT_N + c);
            float4 vv = *(const float4*)(Vg + (size_t)(kt + r) * QKVT_N + c);
            Ks[r * LD + c + 0] = kv.x; Ks[r * LD + c + 1] = kv.y;
            Ks[r * LD + c + 2] = kv.z; Ks[r * LD + c + 3] = kv.w;
            Vs[r * LD + c + 0] = vv.x; Vs[r * LD + c + 1] = vv.y;
            Vs[r * LD + c + 2] = vv.z; Vs[r * LD + c + 3] = vv.w;
        }
        __syncthreads();

        // S = (Q*scale) @ K^T, 8x4 per thread
        float s[8][4];
        #pragma unroll
        for (int i = 0; i < 8; i++)
            #pragma unroll
            for (int j = 0; j < 4; j++) s[i][j] = 0.f;

        #pragma unroll 8
        for (int dd = 0; dd < 64; dd++) {
            float qr[8], kr[4];
            #pragma unroll
            for (int i = 0; i < 8; i++) qr[i] = Qs[(ty * 8 + i) * LD + dd];
            #pragma unroll
            for (int j = 0; j < 4; j++) kr[j] = Ks[(tx * 4 + j) * LD + dd];
            #pragma unroll
            for (int i = 0; i < 8; i++)
                #pragma unroll
                for (int j = 0; j < 4; j++)
                    s[i][j] = fmaf(qr[i], kr[j], s[i][j]);
        }

        // Online softmax per row (stats replicated across the 16-lane group)
        #pragma unroll
        for (int i = 0; i < 8; i++) {
            float mx = fmaxf(fmaxf(s[i][0], s[i][1]), fmaxf(s[i][2], s[i][3]));
            mx = fmaxf(mx, __shfl_xor_sync(0xffffffffu, mx, 1));
            mx = fmaxf(mx, __shfl_xor_sync(0xffffffffu, mx, 2));
            mx = fmaxf(mx, __shfl_xor_sync(0xffffffffu, mx, 4));
            mx = fmaxf(mx, __shfl_xor_sync(0xffffffffu, mx, 8));
            float mn   = fmaxf(m[i], mx);
            float corr = __expf(m[i] - mn);
            float psum = 0.f;
            #pragma unroll
            for (int j = 0; j < 4; j++) {
                float p = __expf(s[i][j] - mn);
                Ps[(ty * 8 + i) * LD + tx * 4 + j] = p;
                psum += p;
            }
            psum += __shfl_xor_sync(0xffffffffu, psum, 1);
            psum += __shfl_xor_sync(0xffffffffu, psum, 2);
            psum += __shfl_xor_sync(0xffffffffu, psum, 4);
            psum += __shfl_xor_sync(0xffffffffu, psum, 8);
            l[i] = l[i] * corr + psum;
            m[i] = mn;
            #pragma unroll
            for (int j = 0; j < 4; j++) O[i][j] *= corr;
        }
        __syncthreads();

        // O += P @ V
        #pragma unroll 8
        for (int jj = 0; jj < BC; jj++) {
            float pv[8], vv[4];
            #pragma unroll
            for (int i = 0; i < 8; i++) pv[i] = Ps[(ty * 8 + i) * LD + jj];
            #pragma unroll
            for (int j = 0; j < 4; j++) vv[j] = Vs[jj * LD + tx * 4 + j];
            #pragma unroll
            for (int i = 0; i < 8; i++)
                #pragma unroll
                for (int j = 0; j < 4; j++)
                    O[i][j] = fmaf(pv[i], vv[j], O[i][j]);
        }
        __syncthreads();
    }

    float* outp = cat + (rowbase + i0) * CAT_N + h * 128;
    #pragma unroll
    for (int i = 0; i < 8; i++) {
        float inv = 1.0f / l[i];
        #pragma unroll
        for (int j = 0; j < 4; j++)
            outp[(size_t)(ty * 8 + i) * CAT_N + tx * 4 + j] = O[i][j] * inv;
    }
}

// ---------------------------------------------------------------------------
// Branch 2 as exponential-decay scan:
//   out2[i] = fwd_i + a*bwd_{i+1},  fwd_i = u_i + a*fwd_{i-1},
//   bwd_i = u_i + a*bwd_{i+1},      u_j = rinv[j] * t[b,j,f].
// Chunked (256 rows/chunk, 96-row halo; a^96 ~ 5e-16). 16384 threads.
// Output into g_cat[row, h*128 + 64 + d].
// ---------------------------------------------------------------------------
__global__ __launch_bounds__(256) void scan_kernel(
    const float* __restrict__ qkvt, float* __restrict__ cat)
{
    const int id    = blockIdx.x * 256 + threadIdx.x;  // 0 .. 16383
    const int colid = id & 2047;                        // b*512 + f
    const int chunk = id >> 11;                         // 0..7
    const int b = colid >> 9;
    const int f = colid & 511;
    const int h = f >> 6, d = f & 63;

    const int HALO = 96, CH = 256;
    const int c0 = chunk * CH;

    const float* tcol = qkvt + (size_t)b * Nn * QKVT_N + 1536 + f;
    float*       ocol = cat  + (size_t)b * Nn * CAT_N + h * 128 + 64 + d;
    const float a = 0.6922006275553464f;   // exp(-1/e)

    float acc = 0.f;
    int jstart = c0 - HALO; if (jstart < 0) jstart = 0;
    for (int j = jstart; j < c0 + CH; j++) {
        float u = g_rinv[j] * tcol[(size_t)j * QKVT_N];
        acc = fmaf(a, acc, u);
        if (j >= c0) ocol[(size_t)j * CAT_N] = acc;
    }

    acc = 0.f;
    int jend = c0 + CH - 1 + HALO; if (jend > Nn - 1) jend = Nn - 1;
    for (int j = jend; j >= c0; j--) {
        float u = g_rinv[j] * tcol[(size_t)j * QKVT_N];
        float prev = acc;                 // bwd_{j+1}
        acc = fmaf(a, acc, u);            // bwd_j
        if (j < c0 + CH)
            ocol[(size_t)j * CAT_N] += a * prev;   // fwd_j + a*bwd_{j+1}
    }
}

// ---------------------------------------------------------------------------
extern "C" void kernel_launch(void* const* d_in, const int* in_sizes, int n_in,
                              void* d_out, int out_size)
{
    const float* x    = (const float*)d_in[0];   // [4,2048,512]
    const float* Wqkv = (const float*)d_in[1];   // [512,2048]
    const float* Wout = (const float*)d_in[2];   // [1024,512]
    const float* bout = (const float*)d_in[3];   // [512]
    float* out = (float*)d_out;                  // [4,2048,512]

    float *qkvt, *cat;
    cudaGetSymbolAddress((void**)&qkvt, g_qkvt);
    cudaGetSymbolAddress((void**)&cat,  g_cat);

    // attn2 column normalizers
    rinv_kernel<<<8, 256>>>();

    // GEMM1: QKVT = X @ W_qkv
    sgemm128<<<dim3(QKVT_N / 128, Mn / 128), 256>>>(
        x, Wqkv, qkvt, nullptr, Mn, QKVT_N, Dn);

    // Branch 1: flash attention -> cat[:, h*128 + 0..63]
    const int FLASH_SMEM = 65 * (128 + 64 + 64 + 128) * 4;  // 99840 B
    cudaFuncSetAttribute(flash_kernel,
                         cudaFuncAttributeMaxDynamicSharedMemorySize, FLASH_SMEM);
    flash_kernel<<<dim3(Nn / 128, Bn * Hn), 256, FLASH_SMEM>>>(qkvt, cat);

    // Branch 2: decay scan -> cat[:, h*128 + 64..127]
    scan_kernel<<<16384 / 256, 256>>>(qkvt, cat);

    // GEMM2: out = cat @ W_out + b_out
    sgemm128<<<dim3(Dn / 128, Mn / 128), 256>>>(
        cat, Wout, out, bout, Mn, Dn, CAT_N);
}

// round 3
// speedup vs baseline: 2.8650x; 2.8650x over previous
#include <cuda_runtime.h>
#include <cstdint>
#include <math.h>

// Problem constants
#define Bn   4
#define Nn   2048
#define Dn   512
#define Hn   8
#define Mn   (Bn * Nn)      // 8192 rows
#define QKVT_N 2048
#define CAT_N  1024

// Scratch (device globals — allocation-free per harness rules)
__device__ float g_qkvt[Mn * QKVT_N];   // 64 MB
__device__ float g_cat [Mn * CAT_N];    // 32 MB
__device__ float g_rinv[Nn];

// ---------------------------------------------------------------------------
__device__ __forceinline__ uint32_t f2tf(float x) {
    uint32_t u; asm("cvt.rna.tf32.f32 %0, %1;" : "=r"(u) : "f"(x)); return u;
}
__device__ __forceinline__ float4 cvt4(float4 v) {
    float4 r;
    r.x = __uint_as_float(f2tf(v.x));
    r.y = __uint_as_float(f2tf(v.y));
    r.z = __uint_as_float(f2tf(v.z));
    r.w = __uint_as_float(f2tf(v.w));
    return r;
}
#define MMA_TF32(d, a, b)                                                      \
    asm volatile(                                                              \
        "mma.sync.aligned.m16n8k8.row.col.f32.tf32.tf32.f32 "                  \
        "{%0,%1,%2,%3},{%4,%5,%6,%7},{%8,%9},{%0,%1,%2,%3};"                   \
        : "+f"((d)[0]), "+f"((d)[1]), "+f"((d)[2]), "+f"((d)[3])               \
        : "r"((a)[0]), "r"((a)[1]), "r"((a)[2]), "r"((a)[3]),                  \
          "r"((b)[0]), "r"((b)[1]))

// ---------------------------------------------------------------------------
// rinv[j] = 1 / sum_k exp(-|j-k|/e), closed form in fp64.
// ---------------------------------------------------------------------------
__global__ void rinv_kernel() {
    int j = blockIdx.x * blockDim.x + threadIdx.x;
    if (j >= Nn) return;
    const double la = -0.36787944117144233;   // -1/e
    const double a  =  0.6922006275553464;    // exp(-1/e)
    double s = 1.0
             + a * (1.0 - exp(la * (double)j))            / (1.0 - a)
             + a * (1.0 - exp(la * (double)(Nn - 1 - j))) / (1.0 - a);
    g_rinv[j] = (float)(1.0 / s);
}

// ---------------------------------------------------------------------------
// tf32 tensor-core GEMM: C[M,N] = A[M,K] @ B[K,N] (+bias).
// Tiles 128x128x32, 8 warps. Warp tile 64x32 (4 m-frags x 4 n-frags m16n8k8).
// As[m][k] ld=36 (bank-free frag reads), Bs[k][n] ld=136 (bank-free).
// ---------------------------------------------------------------------------
__global__ __launch_bounds__(256) void gemm_tf32(
    const float* __restrict__ A, const float* __restrict__ B,
    float* __restrict__ C, const float* __restrict__ bias,
    int M, int N, int K)
{
    __shared__ float As[128][36];
    __shared__ float Bs[32][136];

    const int tid  = threadIdx.x;
    const int brow = blockIdx.y * 128;
    const int bcol = blockIdx.x * 128;

    // Loader mapping
    const int a_r = tid >> 3, a_c = (tid & 7) * 4;      // 32 rows/pass, 4 passes
    const int b_r = tid >> 5, b_c = (tid & 31) * 4;     // 8 rows/pass, 4 passes

    const float* Aptr = A + (size_t)(brow + a_r) * K + a_c;
    const float* Bptr = B + (size_t)b_r * N + bcol + b_c;

    float4 pa[4], pb[4];
    #pragma unroll
    for (int i = 0; i < 4; i++) {
        pa[i] = *(const float4*)(Aptr + (size_t)(32 * i) * K);
        pb[i] = *(const float4*)(Bptr + (size_t)(8 * i) * N);
    }

    const int warp = tid >> 5, lane = tid & 31;
    const int wm = warp >> 2, wn = warp & 3;   // wm: 2 x 64 rows, wn: 4 x 32 cols
    const int r0 = lane >> 2, c0 = lane & 3;

    float acc[4][4][4];
    #pragma unroll
    for (int im = 0; im < 4; im++)
        #pragma unroll
        for (int jn = 0; jn < 4; jn++)
            #pragma unroll
            for (int q = 0; q < 4; q++) acc[im][jn][q] = 0.f;

    for (int k0 = 0; k0 < K; k0 += 32) {
        #pragma unroll
        for (int i = 0; i < 4; i++) {
            *(float4*)&As[a_r + 32 * i][a_c] = cvt4(pa[i]);
            *(float4*)&Bs[b_r +  8 * i][b_c] = cvt4(pb[i]);
        }
        __syncthreads();

        if (k0 + 32 < K) {
            #pragma unroll
            for (int i = 0; i < 4; i++) {
                pa[i] = *(const float4*)(Aptr + (size_t)(32 * i) * K + k0 + 32);
                pb[i] = *(const float4*)(Bptr + (size_t)(k0 + 32 + 8 * i) * N);
            }
        }

        #pragma unroll
        for (int kk = 0; kk < 4; kk++) {
            uint32_t a[4][4], b[4][2];
            #pragma unroll
            for (int im = 0; im < 4; im++) {
                const int row = wm * 64 + im * 16 + r0;
                const int kc  = kk * 8 + c0;
                a[im][0] = __float_as_uint(As[row    ][kc    ]);
                a[im][1] = __float_as_uint(As[row + 8][kc    ]);
                a[im][2] = __float_as_uint(As[row    ][kc + 4]);
                a[im][3] = __float_as_uint(As[row + 8][kc + 4]);
            }
            #pragma unroll
            for (int jn = 0; jn < 4; jn++) {
                const int col = wn * 32 + jn * 8 + r0;
                b[jn][0] = __float_as_uint(Bs[kk * 8 + c0    ][col]);
                b[jn][1] = __float_as_uint(Bs[kk * 8 + c0 + 4][col]);
            }
            #pragma unroll
            for (int im = 0; im < 4; im++)
                #pragma unroll
                for (int jn = 0; jn < 4; jn++)
                    MMA_TF32(acc[im][jn], a[im], b[jn]);
        }
        __syncthreads();
    }

    // Epilogue
    #pragma unroll
    for (int jn = 0; jn < 4; jn++) {
        const int col = bcol + wn * 32 + jn * 8 + 2 * c0;
        float bx = 0.f, by = 0.f;
        if (bias) { bx = bias[col]; by = bias[col + 1]; }
        #pragma unroll
        for (int im = 0; im < 4; im++) {
            const int row = brow + wm * 64 + im * 16 + r0;
            float2 v0 = { acc[im][jn][0] + bx, acc[im][jn][1] + by };
            float2 v1 = { acc[im][jn][2] + bx, acc[im][jn][3] + by };
            *(float2*)&C[(size_t)row       * N + col] = v0;
            *(float2*)&C[(size_t)(row + 8) * N + col] = v1;
        }
    }
}

// ---------------------------------------------------------------------------
// Flash attention (branch 1) on tf32 tensor cores.
// BR=128 rows/block (8 warps x 16 rows), BC=64 keys/tile, DH=64.
// Ks[key][dh] ld=68, Vs[dh][key] ld=68, Ps[row][*] ld=68 (all bank-free).
// ---------------------------------------------------------------------------
__global__ __launch_bounds__(256) void flash_tf32(
    const float* __restrict__ qkvt, float* __restrict__ cat)
{
    constexpr int LD = 68;
    extern __shared__ float sm[];
    float* Ks = sm;                    // [64][68]
    float* Vs = Ks + 64 * LD;          // [64][68]  (transposed: [dh][key])
    float* Ps = Vs + 64 * LD;          // [128][68] (Q staging, then P per-warp)

    const int tid  = threadIdx.x;
    const int warp = tid >> 5, lane = tid & 31;
    const int r0 = lane >> 2, c0 = lane & 3;
    const int bh = blockIdx.y;
    const int b  = bh >> 3, h = bh & 7;
    const int i0 = blockIdx.x * 128;
    const float scale = 0.125f;

    const size_t rowbase = (size_t)b * Nn;
    const float* Qg = qkvt + (rowbase + i0) * QKVT_N + h * 64;
    const float* Kg = qkvt + rowbase * QKVT_N + 512  + h * 64;
    const float* Vg = qkvt + rowbase * QKVT_N + 1024 + h * 64;

    // --- Stage Q (scaled, tf32) into Ps, then pull per-warp fragments ---
    {
        const int qr = tid >> 4, qc = (tid & 15) * 4;
        #pragma unroll
        for (int it = 0; it < 8; it++) {
            const int r = qr + it * 16;
            float4 v = *(const float4*)(Qg + (size_t)r * QKVT_N + qc);
            v.x *= scale; v.y *= scale; v.z *= scale; v.w *= scale;
            *(float4*)&Ps[r * LD + qc] = cvt4(v);
        }
    }
    __syncthreads();

    uint32_t q[8][4];
    #pragma unroll
    for (int kk = 0; kk < 8; kk++) {
        const int row = warp * 16 + r0;
        const int kc  = kk * 8 + c0;
        q[kk][0] = __float_as_uint(Ps[ row      * LD + kc    ]);
        q[kk][1] = __float_as_uint(Ps[(row + 8) * LD + kc    ]);
        q[kk][2] = __float_as_uint(Ps[ row      * LD + kc + 4]);
        q[kk][3] = __float_as_uint(Ps[(row + 8) * LD + kc + 4]);
    }

    float o[8][4];
    #pragma unroll
    for (int jn = 0; jn < 8; jn++)
        #pragma unroll
        for (int p = 0; p < 4; p++) o[jn][p] = 0.f;
    float mA = -1e30f, mB = -1e30f, lA = 0.f, lB = 0.f;

    const int lr = tid >> 4, lc = (tid & 15) * 4;   // K/V loader mapping

    for (int kt = 0; kt < Nn; kt += 64) {
        // Load K (natural) and V (transposed) tiles, tf32-converted
        #pragma unroll
        for (int it = 0; it < 4; it++) {
            const int r = lr + it * 16;
            float4 kv = *(const float4*)(Kg + (size_t)(kt + r) * QKVT_N + lc);
            *(float4*)&Ks[r * LD + lc] = cvt4(kv);
            float4 vv = *(const float4*)(Vg + (size_t)(kt + r) * QKVT_N + lc);
            Vs[(lc + 0) * LD + r] = __uint_as_float(f2tf(vv.x));
            Vs[(lc + 1) * LD + r] = __uint_as_float(f2tf(vv.y));
            Vs[(lc + 2) * LD + r] = __uint_as_float(f2tf(vv.z));
            Vs[(lc + 3) * LD + r] = __uint_as_float(f2tf(vv.w));
        }
        __syncthreads();

        // S = Q @ K^T   (16 x 64 per warp)
        float s[8][4];
        #pragma unroll
        for (int jn = 0; jn < 8; jn++)
            #pragma unroll
            for (int p = 0; p < 4; p++) s[jn][p] = 0.f;

        #pragma unroll
        for (int kk = 0; kk < 8; kk++) {
            #pragma unroll
            for (int jn = 0; jn < 8; jn++) {
                uint32_t bb[2];
                const int key = jn * 8 + r0;
                bb[0] = __float_as_uint(Ks[key * LD + kk * 8 + c0    ]);
                bb[1] = __float_as_uint(Ks[key * LD + kk * 8 + c0 + 4]);
                MMA_TF32(s[jn], q[kk], bb);
            }
        }

        // Online softmax (rows r0 and r0+8 of this warp's 16-row strip)
        float mxA = -1e30f, mxB = -1e30f;
        #pragma unroll
        for (int jn = 0; jn < 8; jn++) {
            mxA = fmaxf(mxA, fmaxf(s[jn][0], s[jn][1]));
            mxB = fmaxf(mxB, fmaxf(s[jn][2], s[jn][3]));
        }
        mxA = fmaxf(mxA, __shfl_xor_sync(0xffffffffu, mxA, 1));
        mxA = fmaxf(mxA, __shfl_xor_sync(0xffffffffu, mxA, 2));
        mxB = fmaxf(mxB, __shfl_xor_sync(0xffffffffu, mxB, 1));
        mxB = fmaxf(mxB, __shfl_xor_sync(0xffffffffu, mxB, 2));

        const float mAn = fmaxf(mA, mxA), mBn = fmaxf(mB, mxB);
        const float corrA = __expf(mA - mAn), corrB = __expf(mB - mBn);
        float sumA = 0.f, sumB = 0.f;

        float* PrA = Ps + (warp * 16 + r0    ) * LD;
        float* PrB = Ps + (warp * 16 + r0 + 8) * LD;
        #pragma unroll
        for (int jn = 0; jn < 8; jn++) {
            float p0 = __expf(s[jn][0] - mAn);
            float p1 = __expf(s[jn][1] - mAn);
            float p2 = __expf(s[jn][2] - mBn);
            float p3 = __expf(s[jn][3] - mBn);
            sumA += p0 + p1; sumB += p2 + p3;
            float2 wA = { __uint_as_float(f2tf(p0)), __uint_as_float(f2tf(p1)) };
            float2 wB = { __uint_as_float(f2tf(p2)), __uint_as_float(f2tf(p3)) };
            *(float2*)&PrA[jn * 8 + 2 * c0] = wA;
            *(float2*)&PrB[jn * 8 + 2 * c0] = wB;
        }
        sumA += __shfl_xor_sync(0xffffffffu, sumA, 1);
        sumA += __shfl_xor_sync(0xffffffffu, sumA, 2);
        sumB += __shfl_xor_sync(0xffffffffu, sumB, 1);
        sumB += __shfl_xor_sync(0xffffffffu, sumB, 2);
        lA = lA * corrA + sumA; mA = mAn;
        lB = lB * corrB + sumB; mB = mBn;

        #pragma unroll
        for (int jn = 0; jn < 8; jn++) {
            o[jn][0] *= corrA; o[jn][1] *= corrA;
            o[jn][2] *= corrB; o[jn][3] *= corrB;
        }
        __syncwarp();

        // O += P @ V   (P per-warp in Ps, V transposed in Vs)
        #pragma unroll
        for (int kk2 = 0; kk2 < 8; kk2++) {
            uint32_t a[4];
            const int row = warp * 16 + r0;
            const int kc  = kk2 * 8 + c0;
            a[0] = __float_as_uint(Ps[ row      * LD + kc    ]);
            a[1] = __float_as_uint(Ps[(row + 8) * LD + kc    ]);
            a[2] = __float_as_uint(Ps[ row      * LD + kc + 4]);
            a[3] = __float_as_uint(Ps[(row + 8) * LD + kc + 4]);
            #pragma unroll
            for (int jn = 0; jn < 8; jn++) {
                uint32_t bb[2];
                const int dh = jn * 8 + r0;
                bb[0] = __float_as_uint(Vs[dh * LD + kc    ]);
                bb[1] = __float_as_uint(Vs[dh * LD + kc + 4]);
                MMA_TF32(o[jn], a, bb);
            }
        }
        __syncthreads();
    }

    // Epilogue: normalize and write to cat[:, h*128 + 0..63]
    const float invA = 1.0f / lA, invB = 1.0f / lB;
    float* outp = cat + (rowbase + i0 + warp * 16 + r0) * CAT_N + h * 128;
    #pragma unroll
    for (int jn = 0; jn < 8; jn++) {
        const int col = jn * 8 + 2 * c0;
        float2 vA = { o[jn][0] * invA, o[jn][1] * invA };
        float2 vB = { o[jn][2] * invB, o[jn][3] * invB };
        *(float2*)&outp[col] = vA;
        *(float2*)&outp[(size_t)8 * CAT_N + col] = vB;
    }
}

// ---------------------------------------------------------------------------
// Branch 2 exponential-decay scan. CH=64, HALO=64 (a^64 ~ 6e-11).
// 65536 threads -> 256 blocks.
// ---------------------------------------------------------------------------
__global__ __launch_bounds__(256) void scan_kernel(
    const float* __restrict__ qkvt, float* __restrict__ cat)
{
    const int id    = blockIdx.x * 256 + threadIdx.x;
    const int colid = id & 2047;                        // b*512 + f
    const int chunk = id >> 11;                         // 0..31
    const int b = colid >> 9;
    const int f = colid & 511;
    const int h = f >> 6, d = f & 63;

    const int HALO = 64, CH = 64;
    const int c0 = chunk * CH;

    const float* tcol = qkvt + (size_t)b * Nn * QKVT_N + 1536 + f;
    float*       ocol = cat  + (size_t)b * Nn * CAT_N + h * 128 + 64 + d;
    const float a = 0.6922006275553464f;   // exp(-1/e)

    float acc = 0.f;
    int jstart = c0 - HALO; if (jstart < 0) jstart = 0;
    for (int j = jstart; j < c0 + CH; j++) {
        float u = g_rinv[j] * tcol[(size_t)j * QKVT_N];
        acc = fmaf(a, acc, u);
        if (j >= c0) ocol[(size_t)j * CAT_N] = acc;
    }

    acc = 0.f;
    int jend = c0 + CH - 1 + HALO; if (jend > Nn - 1) jend = Nn - 1;
    for (int j = jend; j >= c0; j--) {
        float u = g_rinv[j] * tcol[(size_t)j * QKVT_N];
        float prev = acc;                 // bwd_{j+1}
        acc = fmaf(a, acc, u);            // bwd_j
        if (j < c0 + CH)
            ocol[(size_t)j * CAT_N] += a * prev;   // fwd_j + a*bwd_{j+1}
    }
}

// ---------------------------------------------------------------------------
extern "C" void kernel_launch(void* const* d_in, const int* in_sizes, int n_in,
                              void* d_out, int out_size)
{
    const float* x    = (const float*)d_in[0];   // [4,2048,512]
    const float* Wqkv = (const float*)d_in[1];   // [512,2048]
    const float* Wout = (const float*)d_in[2];   // [1024,512]
    const float* bout = (const float*)d_in[3];   // [512]
    float* out = (float*)d_out;                  // [4,2048,512]

    float *qkvt, *cat;
    cudaGetSymbolAddress((void**)&qkvt, g_qkvt);
    cudaGetSymbolAddress((void**)&cat,  g_cat);

    rinv_kernel<<<8, 256>>>();

    // GEMM1: QKVT = X @ W_qkv  (tf32 tensor cores)
    gemm_tf32<<<dim3(QKVT_N / 128, Mn / 128), 256>>>(
        x, Wqkv, qkvt, nullptr, Mn, QKVT_N, Dn);

    // Branch 1: flash attention (tf32 tensor cores)
    const int FLASH_SMEM = (64 * 68 * 2 + 128 * 68) * 4;   // 69632 B
    cudaFuncSetAttribute(flash_tf32,
                         cudaFuncAttributeMaxDynamicSharedMemorySize, FLASH_SMEM);
    flash_tf32<<<dim3(Nn / 128, Bn * Hn), 256, FLASH_SMEM>>>(qkvt, cat);

    // Branch 2: decay scan
    scan_kernel<<<65536 / 256, 256>>>(qkvt, cat);

    // GEMM2: out = cat @ W_out + b_out  (tf32 tensor cores)
    gemm_tf32<<<dim3(Dn / 128, Mn / 128), 256>>>(
        cat, Wout, out, bout, Mn, Dn, CAT_N);
}

// round 4
// speedup vs baseline: 4.3707x; 1.5255x over previous
#include <cuda_runtime.h>
#include <cuda_fp16.h>
#include <cstdint>
#include <math.h>

// Problem constants
#define Bn   4
#define Nn   2048
#define Dn   512
#define Hn   8
#define Mn   (Bn * Nn)      // 8192 rows
#define QKVT_N 2048
#define CAT_N  1024

// Scratch (device globals — allocation-free per harness rules)
__device__ half g_qkvt[Mn * QKVT_N];   // 32 MB
__device__ half g_cat [Mn * CAT_N];    // 16 MB

__device__ __forceinline__ uint32_t h2u(half2 v) {
    return *reinterpret_cast<uint32_t*>(&v);
}

#define MMA_F16(d, a, b)                                                       \
    asm volatile(                                                              \
        "mma.sync.aligned.m16n8k16.row.col.f32.f16.f16.f32 "                   \
        "{%0,%1,%2,%3},{%4,%5,%6,%7},{%8,%9},{%0,%1,%2,%3};"                   \
        : "+f"((d)[0]), "+f"((d)[1]), "+f"((d)[2]), "+f"((d)[3])               \
        : "r"((a)[0]), "r"((a)[1]), "r"((a)[2]), "r"((a)[3]),                  \
          "r"((b)[0]), "r"((b)[1]))

// ---------------------------------------------------------------------------
// fp16 tensor-core GEMM: C[M,N] = A[M,K] @ B[K,N] (+bias for float C).
// Block tile 128x128x32, 8 warps, warp tile 64x32 (4m x 4n m16n8k16 frags).
// As[m][k] ld=40 halves, Bs[n][k] ld=40 (transposed store) — mainloop
// fragment LDS.32 reads are bank-conflict-free.
// TA: float (convert on load) or half (direct). TC: half or float(+bias).
// ---------------------------------------------------------------------------
template<typename TA, typename TC>
__global__ __launch_bounds__(256) void gemm_f16(
    const TA* __restrict__ A, const float* __restrict__ B,
    TC* __restrict__ C, const float* __restrict__ bias,
    int M, int N, int K)
{
    __shared__ half As[128][40];
    __shared__ half Bs[128][40];   // [n][k]

    const int tid  = threadIdx.x;
    const int brow = blockIdx.y * 128;
    const int bcol = blockIdx.x * 128;

    // A loader: rows a_r + 32i, k-cols a_c..a_c+3
    const int a_r = tid >> 3, a_c = (tid & 7) * 4;
    // B loader: n fixed, k-groups of 4
    const int b_n = tid & 127, b_kg = tid >> 7;

    const TA* Aptr = A + (size_t)(brow + a_r) * K + a_c;
    const float* Bcol = B + bcol + b_n;

    // Prefetch registers
    float4 paf[4]; uint2 pah[4];   // A (one of them used per TA)
    float  pb[4][4];               // B: 4 passes x 4 k

    #pragma unroll
    for (int i = 0; i < 4; i++) {
        if constexpr (sizeof(TA) == 4)
            paf[i] = *(const float4*)(Aptr + (size_t)(32 * i) * K);
        else
            pah[i] = *(const uint2*)(Aptr + (size_t)(32 * i) * K);
        const int k0 = (b_kg + 2 * i) * 4;
        #pragma unroll
        for (int j = 0; j < 4; j++)
            pb[i][j] = Bcol[(size_t)(k0 + j) * N];
    }

    const int warp = tid >> 5, lane = tid & 31;
    const int wm = warp >> 2, wn = warp & 3;
    const int r0 = lane >> 2, c0 = lane & 3;

    float acc[4][4][4];
    #pragma unroll
    for (int im = 0; im < 4; im++)
        #pragma unroll
        for (int jn = 0; jn < 4; jn++)
            #pragma unroll
            for (int q = 0; q < 4; q++) acc[im][jn][q] = 0.f;

    for (int kt = 0; kt < K; kt += 32) {
        // Stage prefetched data into smem (convert to half if needed)
        #pragma unroll
        for (int i = 0; i < 4; i++) {
            if constexpr (sizeof(TA) == 4) {
                half2 h01 = __floats2half2_rn(paf[i].x, paf[i].y);
                half2 h23 = __floats2half2_rn(paf[i].z, paf[i].w);
                uint2 u = { h2u(h01), h2u(h23) };
                *(uint2*)&As[a_r + 32 * i][a_c] = u;
            } else {
                *(uint2*)&As[a_r + 32 * i][a_c] = pah[i];
            }
            const int k0 = (b_kg + 2 * i) * 4;
            half2 h01 = __floats2half2_rn(pb[i][0], pb[i][1]);
            half2 h23 = __floats2half2_rn(pb[i][2], pb[i][3]);
            uint2 u = { h2u(h01), h2u(h23) };
            *(uint2*)&Bs[b_n][k0] = u;
        }
        __syncthreads();

        if (kt + 32 < K) {
            #pragma unroll
            for (int i = 0; i < 4; i++) {
                if constexpr (sizeof(TA) == 4)
                    paf[i] = *(const float4*)(Aptr + (size_t)(32 * i) * K + kt + 32);
                else
                    pah[i] = *(const uint2*)(Aptr + (size_t)(32 * i) * K + kt + 32);
                const int k0 = (b_kg + 2 * i) * 4;
                #pragma unroll
                for (int j = 0; j < 4; j++)
                    pb[i][j] = Bcol[(size_t)(kt + 32 + k0 + j) * N];
            }
        }

        #pragma unroll
        for (int kk = 0; kk < 2; kk++) {
            uint32_t a[4][4], b[4][2];
            const int kc = kk * 16 + 2 * c0;
            #pragma unroll
            for (int im = 0; im < 4; im++) {
                const int row = wm * 64 + im * 16 + r0;
                a[im][0] = *(const uint32_t*)&As[row    ][kc    ];
                a[im][1] = *(const uint32_t*)&As[row + 8][kc    ];
                a[im][2] = *(const uint32_t*)&As[row    ][kc + 8];
                a[im][3] = *(const uint32_t*)&As[row + 8][kc + 8];
            }
            #pragma unroll
            for (int jn = 0; jn < 4; jn++) {
                const int col = wn * 32 + jn * 8 + r0;
                b[jn][0] = *(const uint32_t*)&Bs[col][kc    ];
                b[jn][1] = *(const uint32_t*)&Bs[col][kc + 8];
            }
            #pragma unroll
            for (int im = 0; im < 4; im++)
                #pragma unroll
                for (int jn = 0; jn < 4; jn++)
                    MMA_F16(acc[im][jn], a[im], b[jn]);
        }
        __syncthreads();
    }

    // Epilogue
    #pragma unroll
    for (int jn = 0; jn < 4; jn++) {
        const int col = bcol + wn * 32 + jn * 8 + 2 * c0;
        float bx = 0.f, by = 0.f;
        if (bias) { bx = bias[col]; by = bias[col + 1]; }
        #pragma unroll
        for (int im = 0; im < 4; im++) {
            const int row = brow + wm * 64 + im * 16 + r0;
            if constexpr (sizeof(TC) == 4) {
                float2 v0 = { acc[im][jn][0] + bx, acc[im][jn][1] + by };
                float2 v1 = { acc[im][jn][2] + bx, acc[im][jn][3] + by };
                *(float2*)&C[(size_t)row       * N + col] = v0;
                *(float2*)&C[(size_t)(row + 8) * N + col] = v1;
            } else {
                *(half2*)&C[(size_t)row       * N + col] =
                    __floats2half2_rn(acc[im][jn][0], acc[im][jn][1]);
                *(half2*)&C[(size_t)(row + 8) * N + col] =
                    __floats2half2_rn(acc[im][jn][2], acc[im][jn][3]);
            }
        }
    }
}

// ---------------------------------------------------------------------------
// Flash attention (branch 1) on fp16 tensor cores, no-max softmax.
// BR=128 (8 warps x 16 rows), BC=64 keys/tile, DH=64.
// Ks[key][dh] ld=72, Vs[dh][key] ld=72, Ps[row][key] ld=72 — frag LDS
// bank-conflict-free. Q fragments loaded directly from gmem.
// ---------------------------------------------------------------------------
__global__ __launch_bounds__(256) void flash_f16(
    const half* __restrict__ qkvt, half* __restrict__ cat)
{
    __shared__ half Ks[64][72];
    __shared__ half Vs[64][72];   // transposed: [dh][key]
    __shared__ half Ps[128][72];

    const int tid  = threadIdx.x;
    const int warp = tid >> 5, lane = tid & 31;
    const int r0 = lane >> 2, c0 = lane & 3;
    const int bh = blockIdx.y;
    const int b  = bh >> 3, h = bh & 7;
    const int i0 = blockIdx.x * 128;

    const size_t rowbase = (size_t)b * Nn;
    const half* Qg = qkvt + (rowbase + i0) * QKVT_N + h * 64;
    const half* Kg = qkvt + rowbase * QKVT_N + 512  + h * 64;
    const half* Vg = qkvt + rowbase * QKVT_N + 1024 + h * 64;

    const int rA = warp * 16 + r0;    // this lane's row (and rA+8)

    // Q fragments straight from gmem, scaled by 1/8 (exact in fp16)
    const half2 sc = __float2half2_rn(0.125f);
    uint32_t q[4][4];
    #pragma unroll
    for (int kk = 0; kk < 4; kk++) {
        const int col = kk * 16 + 2 * c0;
        half2 v0 = __hmul2(*(const half2*)(Qg + (size_t)rA * QKVT_N + col), sc);
        half2 v1 = __hmul2(*(const half2*)(Qg + (size_t)(rA + 8) * QKVT_N + col), sc);
        half2 v2 = __hmul2(*(const half2*)(Qg + (size_t)rA * QKVT_N + col + 8), sc);
        half2 v3 = __hmul2(*(const half2*)(Qg + (size_t)(rA + 8) * QKVT_N + col + 8), sc);
        q[kk][0] = h2u(v0); q[kk][1] = h2u(v1); q[kk][2] = h2u(v2); q[kk][3] = h2u(v3);
    }

    float o[8][4];
    #pragma unroll
    for (int jn = 0; jn < 8; jn++)
        #pragma unroll
        for (int p = 0; p < 4; p++) o[jn][p] = 0.f;
    float lA = 0.f, lB = 0.f;

    const int lr = tid >> 4, lc = (tid & 15) * 4;   // K/V loader mapping

    for (int kt = 0; kt < Nn; kt += 64) {
        // Load K (natural) and V (transposed) tiles
        #pragma unroll
        for (int it = 0; it < 4; it++) {
            const int r = lr + it * 16;
            uint2 kv = *(const uint2*)(Kg + (size_t)(kt + r) * QKVT_N + lc);
            *(uint2*)&Ks[r][lc] = kv;
            uint2 vv = *(const uint2*)(Vg + (size_t)(kt + r) * QKVT_N + lc);
            half2 v01 = *reinterpret_cast<half2*>(&vv.x);
            half2 v23 = *reinterpret_cast<half2*>(&vv.y);
            Vs[lc + 0][r] = __low2half(v01);
            Vs[lc + 1][r] = __high2half(v01);
            Vs[lc + 2][r] = __low2half(v23);
            Vs[lc + 3][r] = __high2half(v23);
        }
        __syncthreads();

        // S = Q @ K^T (16 x 64 per warp)
        float s[8][4];
        #pragma unroll
        for (int jn = 0; jn < 8; jn++)
            #pragma unroll
            for (int p = 0; p < 4; p++) s[jn][p] = 0.f;

        #pragma unroll
        for (int kk = 0; kk < 4; kk++) {
            const int kc = kk * 16 + 2 * c0;
            #pragma unroll
            for (int jn = 0; jn < 8; jn++) {
                uint32_t bb[2];
                const int key = jn * 8 + r0;
                bb[0] = *(const uint32_t*)&Ks[key][kc    ];
                bb[1] = *(const uint32_t*)&Ks[key][kc + 8];
                MMA_F16(s[jn], q[kk], bb);
            }
        }

        // No-max softmax: P = exp(S), accumulate row sums
        float sumA = 0.f, sumB = 0.f;
        #pragma unroll
        for (int jn = 0; jn < 8; jn++) {
            float p0 = __expf(s[jn][0]);
            float p1 = __expf(s[jn][1]);
            float p2 = __expf(s[jn][2]);
            float p3 = __expf(s[jn][3]);
            sumA += p0 + p1; sumB += p2 + p3;
            *(half2*)&Ps[rA    ][jn * 8 + 2 * c0] = __floats2half2_rn(p0, p1);
            *(half2*)&Ps[rA + 8][jn * 8 + 2 * c0] = __floats2half2_rn(p2, p3);
        }
        sumA += __shfl_xor_sync(0xffffffffu, sumA, 1);
        sumA += __shfl_xor_sync(0xffffffffu, sumA, 2);
        sumB += __shfl_xor_sync(0xffffffffu, sumB, 1);
        sumB += __shfl_xor_sync(0xffffffffu, sumB, 2);
        lA += sumA; lB += sumB;
        __syncwarp();

        // O += P @ V
        #pragma unroll
        for (int kk = 0; kk < 4; kk++) {
            const int kc = kk * 16 + 2 * c0;
            uint32_t a[4];
            a[0] = *(const uint32_t*)&Ps[rA    ][kc    ];
            a[1] = *(const uint32_t*)&Ps[rA + 8][kc    ];
            a[2] = *(const uint32_t*)&Ps[rA    ][kc + 8];
            a[3] = *(const uint32_t*)&Ps[rA + 8][kc + 8];
            #pragma unroll
            for (int jn = 0; jn < 8; jn++) {
                uint32_t bb[2];
                const int dh = jn * 8 + r0;
                bb[0] = *(const uint32_t*)&Vs[dh][kc    ];
                bb[1] = *(const uint32_t*)&Vs[dh][kc + 8];
                MMA_F16(o[jn], a, bb);
            }
        }
        __syncthreads();
    }

    // Epilogue: normalize and write half to cat[:, h*128 + 0..63]
    const float invA = 1.0f / lA, invB = 1.0f / lB;
    half* outp = cat + (rowbase + i0 + rA) * CAT_N + h * 128;
    #pragma unroll
    for (int jn = 0; jn < 8; jn++) {
        const int col = jn * 8 + 2 * c0;
        *(half2*)&outp[col] =
            __floats2half2_rn(o[jn][0] * invA, o[jn][1] * invA);
        *(half2*)&outp[(size_t)8 * CAT_N + col] =
            __floats2half2_rn(o[jn][2] * invB, o[jn][3] * invB);
    }
}

// ---------------------------------------------------------------------------
// Branch 2 exponential-decay scan (half in/out), rinv computed per block.
// CH=64, HALO=64 (a^64 ~ 6e-11). 65536 threads; each block = one chunk.
// ---------------------------------------------------------------------------
__global__ __launch_bounds__(256) void scan_kernel(
    const half* __restrict__ qkvt, half* __restrict__ cat)
{
    __shared__ float rs[192];

    const int HALO = 64, CH = 64;
    const int chunk = (blockIdx.x * 256) >> 11;         // constant per block
    const int c0 = chunk * CH;
    const int jbase = c0 - HALO;

    // rinv window [c0-64, c0+127], float closed form
    const float la = -0.36787944117144233f;
    const float a  =  0.6922006275553464f;
    const float g  = a / (1.f - a);
    for (int t = threadIdx.x; t < 192; t += 256) {
        int j = jbase + t;
        if (j >= 0 && j < Nn) {
            float s = 1.f + g * (1.f - __expf(la * (float)j))
                          + g * (1.f - __expf(la * (float)(Nn - 1 - j)));
            rs[t] = 1.f / s;
        }
    }
    __syncthreads();

    const int id    = blockIdx.x * 256 + threadIdx.x;
    const int colid = id & 2047;                        // b*512 + f
    const int b = colid >> 9;
    const int f = colid & 511;
    const int h = f >> 6, d = f & 63;

    const half* tcol = qkvt + (size_t)b * Nn * QKVT_N + 1536 + f;
    half*       ocol = cat  + (size_t)b * Nn * CAT_N + h * 128 + 64 + d;

    float acc = 0.f;
    int jstart = c0 - HALO; if (jstart < 0) jstart = 0;
    for (int j = jstart; j < c0 + CH; j++) {
        float u = rs[j - jbase] * __half2float(tcol[(size_t)j * QKVT_N]);
        acc = fmaf(a, acc, u);
        if (j >= c0) ocol[(size_t)j * CAT_N] = __float2half(acc);
    }

    acc = 0.f;
    int jend = c0 + CH - 1 + HALO; if (jend > Nn - 1) jend = Nn - 1;
    for (int j = jend; j >= c0; j--) {
        float u = rs[j - jbase] * __half2float(tcol[(size_t)j * QKVT_N]);
        float prev = acc;                 // bwd_{j+1}
        acc = fmaf(a, acc, u);            // bwd_j
        if (j < c0 + CH) {
            float cur = __half2float(ocol[(size_t)j * CAT_N]);
            ocol[(size_t)j * CAT_N] = __float2half(cur + a * prev);
        }
    }
}

// ---------------------------------------------------------------------------
extern "C" void kernel_launch(void* const* d_in, const int* in_sizes, int n_in,
                              void* d_out, int out_size)
{
    const float* x    = (const float*)d_in[0];   // [4,2048,512]
    const float* Wqkv = (const float*)d_in[1];   // [512,2048]
    const float* Wout = (const float*)d_in[2];   // [1024,512]
    const float* bout = (const float*)d_in[3];   // [512]
    float* out = (float*)d_out;                  // [4,2048,512]

    half *qkvt, *cat;
    cudaGetSymbolAddress((void**)&qkvt, g_qkvt);
    cudaGetSymbolAddress((void**)&cat,  g_cat);

    // GEMM1: QKVT(half) = X @ W_qkv
    gemm_f16<float, half><<<dim3(QKVT_N / 128, Mn / 128), 256>>>(
        x, Wqkv, qkvt, nullptr, Mn, QKVT_N, Dn);

    // Branch 1: flash attention -> cat[:, h*128 + 0..63]
    flash_f16<<<dim3(Nn / 128, Bn * Hn), 256>>>(qkvt, cat);

    // Branch 2: decay scan -> cat[:, h*128 + 64..127]
    scan_kernel<<<65536 / 256, 256>>>(qkvt, cat);

    // GEMM2: out(float) = cat(half) @ W_out + b_out
    gemm_f16<half, float><<<dim3(Dn / 128, Mn / 128), 256>>>(
        cat, Wout, out, bout, Mn, Dn, CAT_N);
}

// round 5
// speedup vs baseline: 6.5119x; 1.4899x over previous
#include <cuda_runtime.h>
#include <cuda_fp16.h>
#include <cstdint>
#include <math.h>

// Problem constants
#define Bn   4
#define Nn   2048
#define Dn   512
#define Hn   8
#define Mn   (Bn * Nn)      // 8192 rows
#define QKVT_N 2048
#define CAT_N  1024

// Scratch (device globals — allocation-free per harness rules)
__device__ half g_qkvt[Mn * QKVT_N];    // 32 MB
__device__ half g_cat [Mn * CAT_N];     // 16 MB
__device__ half g_xh  [Mn * Dn];        // 8 MB
__device__ half g_wqh [Dn * QKVT_N];    // 2 MB
__device__ half g_woh [CAT_N * Dn];     // 1 MB

__device__ __forceinline__ uint32_t h2u(half2 v) {
    return *reinterpret_cast<uint32_t*>(&v);
}
__device__ __forceinline__ uint32_t s2u(const void* p) {
    return (uint32_t)__cvta_generic_to_shared(p);
}

#define MMA_F16(d, a, b)                                                       \
    asm volatile(                                                              \
        "mma.sync.aligned.m16n8k16.row.col.f32.f16.f16.f32 "                   \
        "{%0,%1,%2,%3},{%4,%5,%6,%7},{%8,%9},{%0,%1,%2,%3};"                   \
        : "+f"((d)[0]), "+f"((d)[1]), "+f"((d)[2]), "+f"((d)[3])               \
        : "r"((a)[0]), "r"((a)[1]), "r"((a)[2]), "r"((a)[3]),                  \
          "r"((b)[0]), "r"((b)[1]))

#define LDSM_X4(r, addr)                                                       \
    asm volatile("ldmatrix.sync.aligned.m8n8.x4.shared.b16 {%0,%1,%2,%3}, [%4];" \
        : "=r"((r)[0]), "=r"((r)[1]), "=r"((r)[2]), "=r"((r)[3]) : "r"(addr))

#define LDSM_X4_T(r, addr)                                                     \
    asm volatile("ldmatrix.sync.aligned.m8n8.x4.trans.shared.b16 {%0,%1,%2,%3}, [%4];" \
        : "=r"((r)[0]), "=r"((r)[1]), "=r"((r)[2]), "=r"((r)[3]) : "r"(addr))

// ---------------------------------------------------------------------------
// float -> half conversion (vectorized), n4 = element_count / 4
// ---------------------------------------------------------------------------
__global__ __launch_bounds__(256) void cvt_f2h(
    const float* __restrict__ src, half* __restrict__ dst, int n4)
{
    int i = blockIdx.x * 256 + threadIdx.x;
    if (i < n4) {
        float4 v = ((const float4*)src)[i];
        uint2 u = { h2u(__floats2half2_rn(v.x, v.y)),
                    h2u(__floats2half2_rn(v.z, v.w)) };
        ((uint2*)dst)[i] = u;
    }
}

// ---------------------------------------------------------------------------
// fp16 tensor-core GEMM with ldmatrix feeds: C[M,N] = A[M,K] @ B[K,N] (+bias).
// Block tile 128x128x64, 8 warps, warp tile 64x32.
// As[m][k] ld=72, Bs[k][n] ld=136 (natural store; b-frags via ldmatrix.trans).
// Both ld's are ≡4 banks mod 32 across ldmatrix row groups -> conflict-free.
// ---------------------------------------------------------------------------
template<typename TC>
__global__ __launch_bounds__(256) void gemm_h(
    const half* __restrict__ A, const half* __restrict__ B,
    TC* __restrict__ C, const float* __restrict__ bias,
    int M, int N, int K)
{
    __shared__ half As[128][72];
    __shared__ half Bs[64][136];

    const int tid  = threadIdx.x;
    const int brow = blockIdx.y * 128;
    const int bcol = blockIdx.x * 128;

    // Loaders: uint4 = 8 halves each, 4 passes
    const int a_r = tid >> 3, a_c = (tid & 7) * 8;    // A: 32 rows/pass
    const int b_r = tid >> 4, b_c = (tid & 15) * 8;   // B: 16 rows/pass

    const half* Aptr = A + (size_t)(brow + a_r) * K + a_c;
    const half* Bptr = B + (size_t)b_r * N + bcol + b_c;

    uint4 pa[4], pb[4];
    #pragma unroll
    for (int i = 0; i < 4; i++) {
        pa[i] = *(const uint4*)(Aptr + (size_t)(32 * i) * K);
        pb[i] = *(const uint4*)(Bptr + (size_t)(16 * i) * N);
    }

    const int warp = tid >> 5, lane = tid & 31;
    const int wm = warp >> 2, wn = warp & 3;          // 2 x 64 rows, 4 x 32 cols
    const int r0 = lane >> 2, c0 = lane & 3;
    const int lq = lane & 7, quad = lane >> 3;

    // ldmatrix per-lane offsets
    const int aRow = (quad & 1) * 8 + lq, aCol = (quad >> 1) * 8;  // A frags
    const int bRow = (quad & 1) * 8 + lq, bCol = (quad >> 1) * 8;  // B trans frags

    float acc[4][4][4];
    #pragma unroll
    for (int im = 0; im < 4; im++)
        #pragma unroll
        for (int jn = 0; jn < 4; jn++)
            #pragma unroll
            for (int q = 0; q < 4; q++) acc[im][jn][q] = 0.f;

    for (int kt = 0; kt < K; kt += 64) {
        #pragma unroll
        for (int i = 0; i < 4; i++) {
            *(uint4*)&As[a_r + 32 * i][a_c] = pa[i];
            *(uint4*)&Bs[b_r + 16 * i][b_c] = pb[i];
        }
        __syncthreads();

        if (kt + 64 < K) {
            #pragma unroll
            for (int i = 0; i < 4; i++) {
                pa[i] = *(const uint4*)(Aptr + (size_t)(32 * i) * K + kt + 64);
                pb[i] = *(const uint4*)(Bptr + (size_t)(kt + 64 + 16 * i) * N);
            }
        }

        #pragma unroll
        for (int kk = 0; kk < 4; kk++) {
            const int kc = kk * 16;
            uint32_t af[4][4];
            #pragma unroll
            for (int im = 0; im < 4; im++)
                LDSM_X4(af[im], s2u(&As[wm * 64 + im * 16 + aRow][kc + aCol]));
            #pragma unroll
            for (int jnp = 0; jnp < 2; jnp++) {
                uint32_t bf[4];
                LDSM_X4_T(bf, s2u(&Bs[kc + bRow][wn * 32 + jnp * 16 + bCol]));
                #pragma unroll
                for (int im = 0; im < 4; im++) {
                    MMA_F16(acc[im][2 * jnp    ], af[im], bf);
                    MMA_F16(acc[im][2 * jnp + 1], af[im], bf + 2);
                }
            }
        }
        __syncthreads();
    }

    // Epilogue
    #pragma unroll
    for (int jn = 0; jn < 4; jn++) {
        const int col = bcol + wn * 32 + jn * 8 + 2 * c0;
        float bx = 0.f, by = 0.f;
        if (bias) { bx = bias[col]; by = bias[col + 1]; }
        #pragma unroll
        for (int im = 0; im < 4; im++) {
            const int row = brow + wm * 64 + im * 16 + r0;
            if constexpr (sizeof(TC) == 4) {
                float2 v0 = { acc[im][jn][0] + bx, acc[im][jn][1] + by };
                float2 v1 = { acc[im][jn][2] + bx, acc[im][jn][3] + by };
                *(float2*)&C[(size_t)row       * N + col] = v0;
                *(float2*)&C[(size_t)(row + 8) * N + col] = v1;
            } else {
                *(half2*)&C[(size_t)row       * N + col] =
                    __floats2half2_rn(acc[im][jn][0], acc[im][jn][1]);
                *(half2*)&C[(size_t)(row + 8) * N + col] =
                    __floats2half2_rn(acc[im][jn][2], acc[im][jn][3]);
            }
        }
    }
}

// ---------------------------------------------------------------------------
// Flash attention (branch 1), fp16 MMA + ldmatrix, no-max softmax,
// register-resident P (S c-frag layout == P@V a-frag layout).
// BR=128 (8 warps x 16 rows), BC=64 keys/tile, DH=64.
// Ks/Vs stored naturally [key][dh] ld=72; K b-frags via ldmatrix,
// V b-frags via ldmatrix.trans (transpose at read).
// ---------------------------------------------------------------------------
__global__ __launch_bounds__(256) void flash_f16(
    const half* __restrict__ qkvt, half* __restrict__ cat)
{
    __shared__ half Ks[64][72];
    __shared__ half Vs[64][72];

    const int tid  = threadIdx.x;
    const int warp = tid >> 5, lane = tid & 31;
    const int r0 = lane >> 2, c0 = lane & 3;
    const int lq = lane & 7, quad = lane >> 3;
    const int bh = blockIdx.y;
    const int b  = bh >> 3, h = bh & 7;
    const int i0 = blockIdx.x * 128;

    const size_t rowbase = (size_t)b * Nn;
    const half* Qg = qkvt + (rowbase + i0) * QKVT_N + h * 64;
    const half* Kg = qkvt + rowbase * QKVT_N + 512  + h * 64;
    const half* Vg = qkvt + rowbase * QKVT_N + 1024 + h * 64;

    const int rA = warp * 16 + r0;

    // Q fragments straight from gmem, scaled by 1/8 (exact in fp16)
    const half2 sc = __float2half2_rn(0.125f);
    uint32_t q[4][4];
    #pragma unroll
    for (int kk = 0; kk < 4; kk++) {
        const int col = kk * 16 + 2 * c0;
        q[kk][0] = h2u(__hmul2(*(const half2*)(Qg + (size_t)rA * QKVT_N + col), sc));
        q[kk][1] = h2u(__hmul2(*(const half2*)(Qg + (size_t)(rA + 8) * QKVT_N + col), sc));
        q[kk][2] = h2u(__hmul2(*(const half2*)(Qg + (size_t)rA * QKVT_N + col + 8), sc));
        q[kk][3] = h2u(__hmul2(*(const half2*)(Qg + (size_t)(rA + 8) * QKVT_N + col + 8), sc));
    }

    float o[8][4];
    #pragma unroll
    for (int jn = 0; jn < 8; jn++)
        #pragma unroll
        for (int p = 0; p < 4; p++) o[jn][p] = 0.f;
    float lA = 0.f, lB = 0.f;

    // K/V tile loader: uint4 = 8 halves, 2 passes of 32 rows
    const int kr = tid >> 3, kc8 = (tid & 7) * 8;

    // ldmatrix per-lane offsets
    const int kRow = (quad >= 2 ? 8 : 0) + lq, kCol = (quad & 1) * 8;  // K frags
    const int vRow = (quad & 1) * 8 + lq,      vCol = (quad >> 1) * 8; // V trans

    for (int kt = 0; kt < Nn; kt += 64) {
        #pragma unroll
        for (int it = 0; it < 2; it++) {
            const int r = kr + it * 32;
            *(uint4*)&Ks[r][kc8] = *(const uint4*)(Kg + (size_t)(kt + r) * QKVT_N + kc8);
            *(uint4*)&Vs[r][kc8] = *(const uint4*)(Vg + (size_t)(kt + r) * QKVT_N + kc8);
        }
        __syncthreads();

        // S = Q @ K^T  (16 x 64 per warp)
        float s[8][4];
        #pragma unroll
        for (int jn = 0; jn < 8; jn++)
            #pragma unroll
            for (int p = 0; p < 4; p++) s[jn][p] = 0.f;

        #pragma unroll
        for (int kk = 0; kk < 4; kk++) {
            const int kc = kk * 16;
            #pragma unroll
            for (int jnp = 0; jnp < 4; jnp++) {
                uint32_t bf[4];
                LDSM_X4(bf, s2u(&Ks[jnp * 16 + kRow][kc + kCol]));
                MMA_F16(s[2 * jnp    ], q[kk], bf);
                MMA_F16(s[2 * jnp + 1], q[kk], bf + 2);
            }
        }

        // P = exp(S) -> half2 fragments in registers (a-frag layout for P@V)
        uint32_t ph[4][4];
        float sumA = 0.f, sumB = 0.f;
        #pragma unroll
        for (int jnp = 0; jnp < 4; jnp++) {
            float p00 = __expf(s[2 * jnp][0]),     p01 = __expf(s[2 * jnp][1]);
            float p02 = __expf(s[2 * jnp][2]),     p03 = __expf(s[2 * jnp][3]);
            float p10 = __expf(s[2 * jnp + 1][0]), p11 = __expf(s[2 * jnp + 1][1]);
            float p12 = __expf(s[2 * jnp + 1][2]), p13 = __expf(s[2 * jnp + 1][3]);
            sumA += (p00 + p01) + (p10 + p11);
            sumB += (p02 + p03) + (p12 + p13);
            ph[jnp][0] = h2u(__floats2half2_rn(p00, p01));
            ph[jnp][1] = h2u(__floats2half2_rn(p02, p03));
            ph[jnp][2] = h2u(__floats2half2_rn(p10, p11));
            ph[jnp][3] = h2u(__floats2half2_rn(p12, p13));
        }
        sumA += __shfl_xor_sync(0xffffffffu, sumA, 1);
        sumA += __shfl_xor_sync(0xffffffffu, sumA, 2);
        sumB += __shfl_xor_sync(0xffffffffu, sumB, 1);
        sumB += __shfl_xor_sync(0xffffffffu, sumB, 2);
        lA += sumA; lB += sumB;

        // O += P @ V  (a-frags = ph, b-frags = ldmatrix.trans of Vs)
        #pragma unroll
        for (int kk2 = 0; kk2 < 4; kk2++) {
            const int kc2 = kk2 * 16;
            #pragma unroll
            for (int jnp = 0; jnp < 4; jnp++) {
                uint32_t bf[4];
                LDSM_X4_T(bf, s2u(&Vs[kc2 + vRow][jnp * 16 + vCol]));
                MMA_F16(o[2 * jnp    ], ph[kk2], bf);
                MMA_F16(o[2 * jnp + 1], ph[kk2], bf + 2);
            }
        }
        __syncthreads();
    }

    // Epilogue: normalize, write half to cat[:, h*128 + 0..63]
    const float invA = 1.0f / lA, invB = 1.0f / lB;
    half* outp = cat + (rowbase + i0 + rA) * CAT_N + h * 128;
    #pragma unroll
    for (int jn = 0; jn < 8; jn++) {
        const int col = jn * 8 + 2 * c0;
        *(half2*)&outp[col] =
            __floats2half2_rn(o[jn][0] * invA, o[jn][1] * invA);
        *(half2*)&outp[(size_t)8 * CAT_N + col] =
            __floats2half2_rn(o[jn][2] * invB, o[jn][3] * invB);
    }
}

// ---------------------------------------------------------------------------
// Branch 2 exponential-decay scan (half in/out), rinv computed per block.
// CH=64, HALO=64 (a^64 ~ 6e-11). 65536 threads; each block = one chunk.
// ---------------------------------------------------------------------------
__global__ __launch_bounds__(256) void scan_kernel(
    const half* __restrict__ qkvt, half* __restrict__ cat)
{
    __shared__ float rs[192];

    const int HALO = 64, CH = 64;
    const int chunk = (blockIdx.x * 256) >> 11;         // constant per block
    const int c0 = chunk * CH;
    const int jbase = c0 - HALO;

    const float la = -0.36787944117144233f;
    const float a  =  0.6922006275553464f;
    const float g  = a / (1.f - a);
    for (int t = threadIdx.x; t < 192; t += 256) {
        int j = jbase + t;
        if (j >= 0 && j < Nn) {
            float s = 1.f + g * (1.f - __expf(la * (float)j))
                          + g * (1.f - __expf(la * (float)(Nn - 1 - j)));
            rs[t] = 1.f / s;
        }
    }
    __syncthreads();

    const int id    = blockIdx.x * 256 + threadIdx.x;
    const int colid = id & 2047;                        // b*512 + f
    const int b = colid >> 9;
    const int f = colid & 511;
    const int h = f >> 6, d = f & 63;

    const half* tcol = qkvt + (size_t)b * Nn * QKVT_N + 1536 + f;
    half*       ocol = cat  + (size_t)b * Nn * CAT_N + h * 128 + 64 + d;

    float acc = 0.f;
    int jstart = c0 - HALO; if (jstart < 0) jstart = 0;
    for (int j = jstart; j < c0 + CH; j++) {
        float u = rs[j - jbase] * __half2float(tcol[(size_t)j * QKVT_N]);
        acc = fmaf(a, acc, u);
        if (j >= c0) ocol[(size_t)j * CAT_N] = __float2half(acc);
    }

    acc = 0.f;
    int jend = c0 + CH - 1 + HALO; if (jend > Nn - 1) jend = Nn - 1;
    for (int j = jend; j >= c0; j--) {
        float u = rs[j - jbase] * __half2float(tcol[(size_t)j * QKVT_N]);
        float prev = acc;                 // bwd_{j+1}
        acc = fmaf(a, acc, u);            // bwd_j
        if (j < c0 + CH) {
            float cur = __half2float(ocol[(size_t)j * CAT_N]);
            ocol[(size_t)j * CAT_N] = __float2half(cur + a * prev);
        }
    }
}

// ---------------------------------------------------------------------------
extern "C" void kernel_launch(void* const* d_in, const int* in_sizes, int n_in,
                              void* d_out, int out_size)
{
    const float* x    = (const float*)d_in[0];   // [4,2048,512]
    const float* Wqkv = (const float*)d_in[1];   // [512,2048]
    const float* Wout = (const float*)d_in[2];   // [1024,512]
    const float* bout = (const float*)d_in[3];   // [512]
    float* out = (float*)d_out;                  // [4,2048,512]

    half *qkvt, *cat, *xh, *wqh, *woh;
    cudaGetSymbolAddress((void**)&qkvt, g_qkvt);
    cudaGetSymbolAddress((void**)&cat,  g_cat);
    cudaGetSymbolAddress((void**)&xh,   g_xh);
    cudaGetSymbolAddress((void**)&wqh,  g_wqh);
    cudaGetSymbolAddress((void**)&woh,  g_woh);

    // Pre-convert inputs to half
    cvt_f2h<<<(Mn * Dn / 4) / 256, 256>>>(x, xh, Mn * Dn / 4);
    cvt_f2h<<<(Dn * QKVT_N / 4) / 256, 256>>>(Wqkv, wqh, Dn * QKVT_N / 4);
    cvt_f2h<<<(CAT_N * Dn / 4) / 256, 256>>>(Wout, woh, CAT_N * Dn / 4);

    // GEMM1: QKVT(half) = Xh @ Wqkvh
    gemm_h<half><<<dim3(QKVT_N / 128, Mn / 128), 256>>>(
        xh, wqh, qkvt, nullptr, Mn, QKVT_N, Dn);

    // Branch 1: flash attention -> cat[:, h*128 + 0..63]
    flash_f16<<<dim3(Nn / 128, Bn * Hn), 256>>>(qkvt, cat);

    // Branch 2: decay scan -> cat[:, h*128 + 64..127]
    scan_kernel<<<65536 / 256, 256>>>(qkvt, cat);

    // GEMM2: out(float) = cat(half) @ Wouth + b_out
    gemm_h<float><<<dim3(Dn / 128, Mn / 128), 256>>>(
        cat, woh, out, bout, Mn, Dn, CAT_N);
}

// round 6
// speedup vs baseline: 7.4709x; 1.1473x over previous
#include <cuda_runtime.h>
#include <cuda_fp16.h>
#include <cstdint>
#include <math.h>

// Problem constants
#define Bn   4
#define Nn   2048
#define Dn   512
#define Hn   8
#define Mn   (Bn * Nn)      // 8192 rows
#define QKVT_N 2048
#define CAT_N  1024

// Scratch (device globals — allocation-free per harness rules)
__device__ half g_qkvt[Mn * QKVT_N];    // 32 MB
__device__ half g_cat [Mn * CAT_N];     // 16 MB
__device__ half g_xh  [Mn * Dn];        // 8 MB
__device__ half g_wqh [Dn * QKVT_N];    // 2 MB
__device__ half g_woh [CAT_N * Dn];     // 1 MB

__device__ __forceinline__ uint32_t h2u(half2 v) {
    return *reinterpret_cast<uint32_t*>(&v);
}
__device__ __forceinline__ uint32_t s2u(const void* p) {
    return (uint32_t)__cvta_generic_to_shared(p);
}

#define MMA_F16(d, a, b)                                                       \
    asm volatile(                                                              \
        "mma.sync.aligned.m16n8k16.row.col.f32.f16.f16.f32 "                   \
        "{%0,%1,%2,%3},{%4,%5,%6,%7},{%8,%9},{%0,%1,%2,%3};"                   \
        : "+f"((d)[0]), "+f"((d)[1]), "+f"((d)[2]), "+f"((d)[3])               \
        : "r"((a)[0]), "r"((a)[1]), "r"((a)[2]), "r"((a)[3]),                  \
          "r"((b)[0]), "r"((b)[1]))

#define LDSM_X4(r, addr)                                                       \
    asm volatile("ldmatrix.sync.aligned.m8n8.x4.shared.b16 {%0,%1,%2,%3}, [%4];" \
        : "=r"((r)[0]), "=r"((r)[1]), "=r"((r)[2]), "=r"((r)[3]) : "r"(addr))

#define LDSM_X4_T(r, addr)                                                     \
    asm volatile("ldmatrix.sync.aligned.m8n8.x4.trans.shared.b16 {%0,%1,%2,%3}, [%4];" \
        : "=r"((r)[0]), "=r"((r)[1]), "=r"((r)[2]), "=r"((r)[3]) : "r"(addr))

#define LDSM_X2_T(r, addr)                                                     \
    asm volatile("ldmatrix.sync.aligned.m8n8.x2.trans.shared.b16 {%0,%1}, [%2];" \
        : "=r"((r)[0]), "=r"((r)[1]) : "r"(addr))

#define CP16(saddr, gptr)                                                      \
    asm volatile("cp.async.cg.shared.global [%0], [%1], 16;"                   \
        :: "r"(saddr), "l"(gptr))
#define CP_COMMIT() asm volatile("cp.async.commit_group;")
#define CP_WAIT1()  asm volatile("cp.async.wait_group 1;")
#define CP_WAIT0()  asm volatile("cp.async.wait_group 0;")

__device__ __forceinline__ uint32_t exp2h2(float x, float y) {
    half2 p = __floats2half2_rn(x, y);
    uint32_t u = h2u(p), d;
    asm("ex2.approx.f16x2 %0, %1;" : "=r"(d) : "r"(u));
    return d;
}

// ---------------------------------------------------------------------------
// Fused float->half conversion of x, W_qkv, W_out (one launch).
// ---------------------------------------------------------------------------
__global__ __launch_bounds__(256) void cvt_all(
    const float* __restrict__ x, const float* __restrict__ wq,
    const float* __restrict__ wo)
{
    const int NX = Mn * Dn / 4;        // 1048576
    const int NQ = Dn * QKVT_N / 4;    // 262144
    const int NO = CAT_N * Dn / 4;     // 131072
    int i = blockIdx.x * 256 + threadIdx.x;
    const float4* src; half* dst; int k;
    if (i < NX)            { src = (const float4*)x;  dst = g_xh;  k = i; }
    else if (i < NX + NQ)  { src = (const float4*)wq; dst = g_wqh; k = i - NX; }
    else                   { src = (const float4*)wo; dst = g_woh; k = i - NX - NQ; }
    float4 v = src[k];
    uint2 u = { h2u(__floats2half2_rn(v.x, v.y)),
                h2u(__floats2half2_rn(v.z, v.w)) };
    ((uint2*)dst)[k] = u;
}

// ---------------------------------------------------------------------------
// fp16 GEMM: C[M,N] = A[M,K] @ B[K,N] (+bias for float C).
// Block tile 128x256, 8 warps of 64x64, K-chunks of 64,
// cp.async double-buffered smem. As[m][k] ld=72, Bs[k][n] ld=264.
// ---------------------------------------------------------------------------
#define GBUF 52224      // per-buffer bytes: As 128*72*2 + Bs 64*264*2
template<typename TC>
__global__ __launch_bounds__(256, 1) void gemm_h(
    const half* __restrict__ A, const half* __restrict__ B,
    TC* __restrict__ C, const float* __restrict__ bias,
    int M, int N, int K)
{
    extern __shared__ char smem[];
    const uint32_t sbase = s2u(smem);

    const int tid  = threadIdx.x;
    const int brow = blockIdx.y * 128;
    const int bcol = blockIdx.x * 256;

    // cp.async loader mapping
    const int a_r = tid >> 3, a_c = (tid & 7) * 8;    // A: 32 rows/pass x4
    const int b_r = tid >> 5, b_c = (tid & 31) * 8;   // B: 8 rows/pass x8

    const half* Aptr = A + (size_t)(brow + a_r) * K + a_c;
    const half* Bptr = B + (size_t)b_r * N + bcol + b_c;
    const uint32_t sAoff = (uint32_t)(a_r * 72 + a_c) * 2;
    const uint32_t sBoff = 128u * 72u * 2u + (uint32_t)(b_r * 264 + b_c) * 2;

    auto issue = [&](int c, int buf) {
        const half* ga = Aptr + c * 64;
        uint32_t sa = sbase + buf * GBUF + sAoff;
        #pragma unroll
        for (int i = 0; i < 4; i++)
            CP16(sa + i * (32 * 72 * 2), ga + (size_t)(32 * i) * K);
        const half* gb = Bptr + (size_t)(c * 64) * N;
        uint32_t sb = sbase + buf * GBUF + sBoff;
        #pragma unroll
        for (int i = 0; i < 8; i++)
            CP16(sb + i * (8 * 264 * 2), gb + (size_t)(8 * i) * N);
        CP_COMMIT();
    };

    const int warp = tid >> 5, lane = tid & 31;
    const int wm = warp >> 2, wn = warp & 3;          // 2 x 64 rows, 4 x 64 cols
    const int r0 = lane >> 2, c0 = lane & 3;
    const int lq = lane & 7, quad = lane >> 3;
    const int aRow = (quad & 1) * 8 + lq, aCol = (quad >> 1) * 8;
    const int bRow = (quad & 1) * 8 + lq, bCol = (quad >> 1) * 8;

    float acc[4][8][4];
    #pragma unroll
    for (int im = 0; im < 4; im++)
        #pragma unroll
        for (int jn = 0; jn < 8; jn++)
            #pragma unroll
            for (int q = 0; q < 4; q++) acc[im][jn][q] = 0.f;

    const int nc = K / 64;
    issue(0, 0);
    issue(1, 1);

    for (int c = 0; c < nc; c++) {
        if (c + 1 < nc) { CP_WAIT1(); } else { CP_WAIT0(); }
        __syncthreads();

        const uint32_t sAu = sbase + (c & 1) * GBUF;
        const uint32_t sBu = sAu + 128u * 72u * 2u;

        #pragma unroll
        for (int kk = 0; kk < 4; kk++) {
            uint32_t af[4][4];
            #pragma unroll
            for (int im = 0; im < 4; im++)
                LDSM_X4(af[im], sAu +
                    ((wm * 64 + im * 16 + aRow) * 72 + kk * 16 + aCol) * 2);
            #pragma unroll
            for (int jnp = 0; jnp < 4; jnp++) {
                uint32_t bf[4];
                LDSM_X4_T(bf, sBu +
                    ((kk * 16 + bRow) * 264 + wn * 64 + jnp * 16 + bCol) * 2);
                #pragma unroll
                for (int im = 0; im < 4; im++) {
                    MMA_F16(acc[im][2 * jnp    ], af[im], bf);
                    MMA_F16(acc[im][2 * jnp + 1], af[im], bf + 2);
                }
            }
        }
        __syncthreads();
        if (c + 2 < nc) issue(c + 2, c & 1);
    }

    // Epilogue
    #pragma unroll
    for (int jn = 0; jn < 8; jn++) {
        const int col = bcol + wn * 64 + jn * 8 + 2 * c0;
        float bx = 0.f, by = 0.f;
        if (bias) { bx = bias[col]; by = bias[col + 1]; }
        #pragma unroll
        for (int im = 0; im < 4; im++) {
            const int row = brow + wm * 64 + im * 16 + r0;
            if constexpr (sizeof(TC) == 4) {
                float2 v0 = { acc[im][jn][0] + bx, acc[im][jn][1] + by };
                float2 v1 = { acc[im][jn][2] + bx, acc[im][jn][3] + by };
                *(float2*)&C[(size_t)row       * N + col] = v0;
                *(float2*)&C[(size_t)(row + 8) * N + col] = v1;
            } else {
                *(half2*)&C[(size_t)row       * N + col] =
                    __floats2half2_rn(acc[im][jn][0], acc[im][jn][1]);
                *(half2*)&C[(size_t)(row + 8) * N + col] =
                    __floats2half2_rn(acc[im][jn][2], acc[im][jn][3]);
            }
        }
    }
}

// ---------------------------------------------------------------------------
// Flash attention (branch 1): fp16 MMA + ldmatrix, no-max softmax,
// register P, row-sum via ones-column of V (fp32 MMA accumulation),
// ex2.approx.f16x2 exponentials, cp.async double-buffered K/V.
// BR=128 (8 warps x 16 rows), BC=64, DH=64.
// ---------------------------------------------------------------------------
__global__ __launch_bounds__(256, 2) void flash_f16(
    const half* __restrict__ qkvt, half* __restrict__ cat)
{
    __shared__ half Ks[2][64][72];
    __shared__ half Vs[2][64][88];   // cols 64..79: [1,0,...] ones-column block

    const int tid  = threadIdx.x;
    const int warp = tid >> 5, lane = tid & 31;
    const int r0 = lane >> 2, c0 = lane & 3;
    const int lq = lane & 7, quad = lane >> 3;
    const int bh = blockIdx.y;
    const int b  = bh >> 3, h = bh & 7;
    const int i0 = blockIdx.x * 128;

    const size_t rowbase = (size_t)b * Nn;
    const half* Qg = qkvt + (rowbase + i0) * QKVT_N + h * 64;
    const half* Kg = qkvt + rowbase * QKVT_N + 512  + h * 64;
    const half* Vg = qkvt + rowbase * QKVT_N + 1024 + h * 64;

    const int rA = warp * 16 + r0;

    // Init ones-column region of V tiles (never touched by cp.async)
    if (tid < 128) {
        int bu = tid >> 6, r = tid & 63;
        uint4 v0 = { 0x00003C00u, 0u, 0u, 0u };   // half2(1,0), zeros
        uint4 z  = { 0u, 0u, 0u, 0u };
        *(uint4*)&Vs[bu][r][64] = v0;
        *(uint4*)&Vs[bu][r][72] = z;
    }

    // Q fragments straight from gmem, scaled by 1/8 (exact in fp16)
    const half2 sc = __float2half2_rn(0.125f);
    uint32_t q[4][4];
    #pragma unroll
    for (int kk = 0; kk < 4; kk++) {
        const int col = kk * 16 + 2 * c0;
        q[kk][0] = h2u(__hmul2(*(const half2*)(Qg + (size_t)rA * QKVT_N + col), sc));
        q[kk][1] = h2u(__hmul2(*(const half2*)(Qg + (size_t)(rA + 8) * QKVT_N + col), sc));
        q[kk][2] = h2u(__hmul2(*(const half2*)(Qg + (size_t)rA * QKVT_N + col + 8), sc));
        q[kk][3] = h2u(__hmul2(*(const half2*)(Qg + (size_t)(rA + 8) * QKVT_N + col + 8), sc));
    }

    float o[8][4];
    #pragma unroll
    for (int jn = 0; jn < 8; jn++)
        #pragma unroll
        for (int p = 0; p < 4; p++) o[jn][p] = 0.f;
    float ol[4] = {0.f, 0.f, 0.f, 0.f};   // l accumulator (ones-column MMA)

    // K/V cp.async loader: 2 passes of 32 rows, 16B each
    const int kr = tid >> 3, kc8 = (tid & 7) * 8;
    auto issueKV = [&](int kt, int buf) {
        #pragma unroll
        for (int it = 0; it < 2; it++) {
            int r = kr + it * 32;
            CP16(s2u(&Ks[buf][r][kc8]), Kg + (size_t)(kt + r) * QKVT_N + kc8);
            CP16(s2u(&Vs[buf][r][kc8]), Vg + (size_t)(kt + r) * QKVT_N + kc8);
        }
        CP_COMMIT();
    };

    const int kRow = (quad >= 2 ? 8 : 0) + lq, kCol = (quad & 1) * 8;
    const int vRow = (quad & 1) * 8 + lq,      vCol = (quad >> 1) * 8;
    const float L2E = 1.4426950408889634f;

    issueKV(0, 0);
    __syncthreads();   // ones-region init visible before first compute

    for (int it = 0; it < Nn / 64; it++) {
        if (it + 1 < Nn / 64) { issueKV((it + 1) * 64, (it + 1) & 1); CP_WAIT1(); }
        else                  { CP_WAIT0(); }
        __syncthreads();
        const int bu = it & 1;

        // S = Q @ K^T  (16 x 64 per warp)
        float s[8][4];
        #pragma unroll
        for (int jn = 0; jn < 8; jn++)
            #pragma unroll
            for (int p = 0; p < 4; p++) s[jn][p] = 0.f;

        #pragma unroll
        for (int kk = 0; kk < 4; kk++) {
            const int kc = kk * 16;
            #pragma unroll
            for (int jnp = 0; jnp < 4; jnp++) {
                uint32_t bf[4];
                LDSM_X4(bf, s2u(&Ks[bu][jnp * 16 + kRow][kc + kCol]));
                MMA_F16(s[2 * jnp    ], q[kk], bf);
                MMA_F16(s[2 * jnp + 1], q[kk], bf + 2);
            }
        }

        // P = exp(S) = exp2(S*log2e), packed half2 a-frags
        uint32_t ph[4][4];
        #pragma unroll
        for (int jnp = 0; jnp < 4; jnp++) {
            ph[jnp][0] = exp2h2(s[2*jnp  ][0]*L2E, s[2*jnp  ][1]*L2E);
            ph[jnp][1] = exp2h2(s[2*jnp  ][2]*L2E, s[2*jnp  ][3]*L2E);
            ph[jnp][2] = exp2h2(s[2*jnp+1][0]*L2E, s[2*jnp+1][1]*L2E);
            ph[jnp][3] = exp2h2(s[2*jnp+1][2]*L2E, s[2*jnp+1][3]*L2E);
        }

        // O += P @ V ; l += P @ ones (cols 64..71, one MMA per kk2)
        #pragma unroll
        for (int kk2 = 0; kk2 < 4; kk2++) {
            const int kc2 = kk2 * 16;
            #pragma unroll
            for (int jnp = 0; jnp < 4; jnp++) {
                uint32_t bf[4];
                LDSM_X4_T(bf, s2u(&Vs[bu][kc2 + vRow][jnp * 16 + vCol]));
                MMA_F16(o[2 * jnp    ], ph[kk2], bf);
                MMA_F16(o[2 * jnp + 1], ph[kk2], bf + 2);
            }
            uint32_t bl[2];
            LDSM_X2_T(bl, s2u(&Vs[bu][kc2 + (lane & 15)][64]));
            MMA_F16(ol, ph[kk2], bl);
        }
        __syncthreads();
    }

    // l lives in lanes with c0==0 (column 64); broadcast within row group
    const float lA = __shfl_sync(0xffffffffu, ol[0], lane & ~3);
    const float lB = __shfl_sync(0xffffffffu, ol[2], lane & ~3);
    const float invA = 1.0f / lA, invB = 1.0f / lB;

    half* outp = cat + (rowbase + i0 + rA) * CAT_N + h * 128;
    #pragma unroll
    for (int jn = 0; jn < 8; jn++) {
        const int col = jn * 8 + 2 * c0;
        *(half2*)&outp[col] =
            __floats2half2_rn(o[jn][0] * invA, o[jn][1] * invA);
        *(half2*)&outp[(size_t)8 * CAT_N + col] =
            __floats2half2_rn(o[jn][2] * invB, o[jn][3] * invB);
    }
}

// ---------------------------------------------------------------------------
// Branch 2 exponential-decay scan, register-buffered (single write pass).
// CH=64, HALO=64 (a^64 ~ 6e-11). 256 blocks x 256 threads.
// ---------------------------------------------------------------------------
__global__ __launch_bounds__(256) void scan_kernel(
    const half* __restrict__ qkvt, half* __restrict__ cat)
{
    __shared__ float rs[192];

    const int chunk = (blockIdx.x * 256) >> 11;         // constant per block
    const int c0 = chunk * 64;
    const int jbase = c0 - 64;

    const float la = -0.36787944117144233f;
    const float a  =  0.6922006275553464f;
    const float g  = a / (1.f - a);
    for (int t = threadIdx.x; t < 192; t += 256) {
        int j = jbase + t;
        if (j >= 0 && j < Nn) {
            float s = 1.f + g * (1.f - __expf(la * (float)j))
                          + g * (1.f - __expf(la * (float)(Nn - 1 - j)));
            rs[t] = 1.f / s;
        }
    }
    __syncthreads();

    const int id    = blockIdx.x * 256 + threadIdx.x;
    const int colid = id & 2047;                        // b*512 + f
    const int b = colid >> 9;
    const int f = colid & 511;
    const int h = f >> 6, d = f & 63;

    const half* tcol = qkvt + (size_t)b * Nn * QKVT_N + 1536 + f;
    half*       ocol = cat  + (size_t)b * Nn * CAT_N + h * 128 + 64 + d;

    float fwd[64], xu[64];
    float acc = 0.f;
    #pragma unroll
    for (int i = 0; i < 64; i++) {            // fwd halo
        int j = c0 - 64 + i;
        float u = 0.f;
        if (j >= 0) u = rs[i] * __half2float(tcol[(size_t)j * QKVT_N]);
        acc = fmaf(a, acc, u);
    }
    #pragma unroll
    for (int i = 0; i < 64; i++) {            // fwd main (cache u)
        float u = rs[64 + i] * __half2float(tcol[(size_t)(c0 + i) * QKVT_N]);
        xu[i] = u;
        acc = fmaf(a, acc, u);
        fwd[i] = acc;
    }
    acc = 0.f;
    #pragma unroll
    for (int i = 63; i >= 0; i--) {           // bwd halo
        int j = c0 + 64 + i;
        float u = 0.f;
        if (j < Nn) u = rs[128 + i] * __half2float(tcol[(size_t)j * QKVT_N]);
        acc = fmaf(a, acc, u);
    }
    #pragma unroll
    for (int i = 63; i >= 0; i--) {           // bwd main + single write
        float prev = acc;                     // bwd_{j+1}
        ocol[(size_t)(c0 + i) * CAT_N] = __float2half(fwd[i] + a * prev);
        acc = fmaf(a, acc, xu[i]);
    }
}

// ---------------------------------------------------------------------------
extern "C" void kernel_launch(void* const* d_in, const int* in_sizes, int n_in,
                              void* d_out, int out_size)
{
    const float* x    = (const float*)d_in[0];   // [4,2048,512]
    const float* Wqkv = (const float*)d_in[1];   // [512,2048]
    const float* Wout = (const float*)d_in[2];   // [1024,512]
    const float* bout = (const float*)d_in[3];   // [512]
    float* out = (float*)d_out;                  // [4,2048,512]

    half *qkvt, *cat, *xh, *wqh, *woh;
    cudaGetSymbolAddress((void**)&qkvt, g_qkvt);
    cudaGetSymbolAddress((void**)&cat,  g_cat);
    cudaGetSymbolAddress((void**)&xh,   g_xh);
    cudaGetSymbolAddress((void**)&wqh,  g_wqh);
    cudaGetSymbolAddress((void**)&woh,  g_woh);

    // Convert all fp32 inputs to half (one launch)
    cvt_all<<<(Mn * Dn + Dn * QKVT_N + CAT_N * Dn) / 4 / 256, 256>>>(
        x, Wqkv, Wout);

    const int GS = 2 * GBUF;   // 104448 B dynamic smem
    cudaFuncSetAttribute(gemm_h<half>,
                         cudaFuncAttributeMaxDynamicSharedMemorySize, GS);
    cudaFuncSetAttribute(gemm_h<float>,
                         cudaFuncAttributeMaxDynamicSharedMemorySize, GS);

    // GEMM1: QKVT(half) = Xh @ Wqkvh
    gemm_h<half><<<dim3(QKVT_N / 256, Mn / 128), 256, GS>>>(
        xh, wqh, qkvt, nullptr, Mn, QKVT_N, Dn);

    // Branch 1: flash attention -> cat[:, h*128 + 0..63]
    flash_f16<<<dim3(Nn / 128, Bn * Hn), 256>>>(qkvt, cat);

    // Branch 2: decay scan -> cat[:, h*128 + 64..127]
    scan_kernel<<<65536 / 256, 256>>>(qkvt, cat);

    // GEMM2: out(float) = cat(half) @ Wouth + b_out
    gemm_h<float><<<dim3(Dn / 256, Mn / 128), 256, GS>>>(
        cat, woh, out, bout, Mn, Dn, CAT_N);
}